// round 1
// baseline (speedup 1.0000x reference)
#include <cuda_runtime.h>
#include <math.h>

#define BB   2048
#define TT   256
#define EMB  128
#define NH   256
#define NCLASS 32000

// -------- persistent scratch (static device globals; no allocation) --------
__device__ float g_xs[(size_t)TT * BB * EMB];   // [t][b][k] embedded inputs, 268MB
__device__ float g_h1[2][BB * NH];              // double-buffered layer-1 hidden
__device__ float g_h2[2][BB * NH];              // double-buffered layer-2 hidden
__device__ float g_c1[BB * NH];
__device__ float g_c2[BB * NH];

// -------- embedding gather: xs[t][b][:] = C[X[b][t]][:] --------
__global__ void embed_kernel(const int* __restrict__ X, const float* __restrict__ C) {
    const size_t total = (size_t)TT * BB * (EMB / 4);
    for (size_t q = (size_t)blockIdx.x * blockDim.x + threadIdx.x; q < total;
         q += (size_t)gridDim.x * blockDim.x) {
        int k4 = (int)(q & 31);            // EMB/4 = 32
        size_t rest = q >> 5;
        int b = (int)(rest & (BB - 1));    // BB = 2048 (pow2)
        int t = (int)(rest >> 11);
        int tok = X[(size_t)b * TT + t];
        float4 v = ((const float4*)C)[(size_t)tok * 32 + k4];
        ((float4*)g_xs)[q] = v;
    }
}

__global__ void zero_states() {
    const int n = BB * NH;
    for (int i = blockIdx.x * blockDim.x + threadIdx.x; i < n; i += gridDim.x * blockDim.x) {
        g_h1[0][i] = 0.f;
        g_h2[0][i] = 0.f;
        g_c1[i] = 0.f;
        g_c2[i] = 0.f;
    }
}

// -------- fused LSTM step: gates = inA*U + inB*V + b, then cell update --------
// CTA tile: 32 rows (batch) x 64 cols (of NH) x 4 gates. 256 threads,
// each thread: 2 rows x 4 cols x 4 gates = 32 accumulators.
__global__ __launch_bounds__(256) void lstm_step(
    int layer, int t,
    const float* __restrict__ Ui, const float* __restrict__ Uf,
    const float* __restrict__ Uc, const float* __restrict__ Uo,
    const float* __restrict__ Vi, const float* __restrict__ Vf,
    const float* __restrict__ Vc, const float* __restrict__ Vo,
    const float* __restrict__ bi, const float* __restrict__ bf,
    const float* __restrict__ bc, const float* __restrict__ bo)
{
    __shared__ __align__(16) float sA[32][34];       // [k][row], padded
    __shared__ __align__(16) float sW[4][32][64];    // [gate][k][col]

    const float* inA; int KA; const float* inB; float* cst; float* hout;
    if (layer == 0) {
        inA = g_xs + (size_t)t * BB * EMB; KA = EMB;
        inB = g_h1[t & 1]; cst = g_c1; hout = g_h1[(t + 1) & 1];
    } else {
        inA = g_h1[(t + 1) & 1]; KA = NH;
        inB = g_h2[t & 1]; cst = g_c2; hout = g_h2[(t + 1) & 1];
    }

    const int tid = threadIdx.x;
    const int tc = tid & 15;     // 0..15 -> 4 cols each
    const int tr = tid >> 4;     // 0..15 -> 2 rows each
    const int mBase = blockIdx.y * 32;
    const int nBase = blockIdx.x * 64;

    float acc[4][2][4];
    #pragma unroll
    for (int g = 0; g < 4; ++g)
        #pragma unroll
        for (int r = 0; r < 2; ++r)
            #pragma unroll
            for (int j = 0; j < 4; ++j) acc[g][r][j] = 0.f;

    #pragma unroll 1
    for (int seg = 0; seg < 2; ++seg) {
        const float* In = seg ? inB : inA;
        const int K = seg ? NH : KA;
        const float* W0 = seg ? Vi : Ui;
        const float* W1 = seg ? Vf : Uf;
        const float* W2 = seg ? Vc : Uc;
        const float* W3 = seg ? Vo : Uo;

        #pragma unroll 1
        for (int kb = 0; kb < K; kb += 32) {
            // stage A tile (transposed): 32 rows x 32 k
            {
                int r = tid >> 3, kq = tid & 7;
                float4 v = *(const float4*)&In[(size_t)(mBase + r) * K + kb + kq * 4];
                sA[kq * 4 + 0][r] = v.x;
                sA[kq * 4 + 1][r] = v.y;
                sA[kq * 4 + 2][r] = v.z;
                sA[kq * 4 + 3][r] = v.w;
            }
            // stage 4 gate weight tiles: each 32k x 64n
            #pragma unroll
            for (int i = 0; i < 8; ++i) {
                const float* W = (i < 2) ? W0 : (i < 4) ? W1 : (i < 6) ? W2 : W3;
                int rem = (i & 1) * 256 + tid;
                int k = rem >> 4, n4 = rem & 15;
                float4 v = *(const float4*)&W[(size_t)(kb + k) * NH + nBase + n4 * 4];
                *(float4*)&sW[i >> 1][k][n4 * 4] = v;
            }
            __syncthreads();

            #pragma unroll
            for (int k = 0; k < 32; ++k) {
                float2 a = *(const float2*)&sA[k][tr * 2];
                #pragma unroll
                for (int g = 0; g < 4; ++g) {
                    float4 w = *(const float4*)&sW[g][k][tc * 4];
                    acc[g][0][0] += a.x * w.x; acc[g][0][1] += a.x * w.y;
                    acc[g][0][2] += a.x * w.z; acc[g][0][3] += a.x * w.w;
                    acc[g][1][0] += a.y * w.x; acc[g][1][1] += a.y * w.y;
                    acc[g][1][2] += a.y * w.z; acc[g][1][3] += a.y * w.w;
                }
            }
            __syncthreads();
        }
    }

    // fused LSTM cell epilogue
    #pragma unroll
    for (int r = 0; r < 2; ++r) {
        int row = mBase + tr * 2 + r;
        size_t off = (size_t)row * NH;
        #pragma unroll
        for (int j = 0; j < 4; ++j) {
            int n = nBase + tc * 4 + j;
            float pi = acc[0][r][j] + bi[n];
            float pf = acc[1][r][j] + bf[n];
            float pg = acc[2][r][j] + bc[n];
            float po = acc[3][r][j] + bo[n];
            float gi = 1.f / (1.f + expf(-pi));
            float gf = 1.f / (1.f + expf(-pf));
            float gg = tanhf(pg);
            float go = 1.f / (1.f + expf(-po));
            float cn = cst[off + n] * gf + gi * gg;
            cst[off + n] = cn;
            hout[off + n] = go * tanhf(cn);
        }
    }
}

// -------- output GEMM: out = h2 @ W_out + b_out  ([2048,256]x[256,32000]) ----
__global__ __launch_bounds__(256) void out_gemm(const float* __restrict__ Wout,
                                                const float* __restrict__ bout,
                                                float* __restrict__ out)
{
    __shared__ __align__(16) float sA[32][68];
    __shared__ __align__(16) float sW[32][64];

    const int tid = threadIdx.x;
    const int tc = tid & 15, tr = tid >> 4;
    const int mBase = blockIdx.y * 64;
    const int nBase = blockIdx.x * 64;
    const float* h2 = g_h2[0];   // after 256 steps, final state lands in buffer 0

    float acc[4][4];
    #pragma unroll
    for (int i = 0; i < 4; ++i)
        #pragma unroll
        for (int j = 0; j < 4; ++j) acc[i][j] = 0.f;

    #pragma unroll 1
    for (int kb = 0; kb < NH; kb += 32) {
        #pragma unroll
        for (int i = 0; i < 2; ++i) {
            int idx = tid + i * 256;
            int r = idx >> 3, kq = idx & 7;
            float4 v = *(const float4*)&h2[(size_t)(mBase + r) * NH + kb + kq * 4];
            sA[kq * 4 + 0][r] = v.x;
            sA[kq * 4 + 1][r] = v.y;
            sA[kq * 4 + 2][r] = v.z;
            sA[kq * 4 + 3][r] = v.w;
        }
        #pragma unroll
        for (int i = 0; i < 2; ++i) {
            int idx = tid + i * 256;
            int k = idx >> 4, n4 = idx & 15;
            float4 v = *(const float4*)&Wout[(size_t)(kb + k) * NCLASS + nBase + n4 * 4];
            *(float4*)&sW[k][n4 * 4] = v;
        }
        __syncthreads();

        #pragma unroll
        for (int k = 0; k < 32; ++k) {
            float4 a = *(const float4*)&sA[k][tr * 4];
            float4 w = *(const float4*)&sW[k][tc * 4];
            acc[0][0] += a.x * w.x; acc[0][1] += a.x * w.y; acc[0][2] += a.x * w.z; acc[0][3] += a.x * w.w;
            acc[1][0] += a.y * w.x; acc[1][1] += a.y * w.y; acc[1][2] += a.y * w.z; acc[1][3] += a.y * w.w;
            acc[2][0] += a.z * w.x; acc[2][1] += a.z * w.y; acc[2][2] += a.z * w.z; acc[2][3] += a.z * w.w;
            acc[3][0] += a.w * w.x; acc[3][1] += a.w * w.y; acc[3][2] += a.w * w.z; acc[3][3] += a.w * w.w;
        }
        __syncthreads();
    }

    float4 b4 = *(const float4*)&bout[nBase + tc * 4];
    #pragma unroll
    for (int i = 0; i < 4; ++i) {
        size_t row = (size_t)(mBase + tr * 4 + i);
        float4 o;
        o.x = acc[i][0] + b4.x;
        o.y = acc[i][1] + b4.y;
        o.z = acc[i][2] + b4.z;
        o.w = acc[i][3] + b4.w;
        *(float4*)&out[row * NCLASS + nBase + tc * 4] = o;
    }
}

// -------- launch --------
extern "C" void kernel_launch(void* const* d_in, const int* in_sizes, int n_in,
                              void* d_out, int out_size) {
    (void)in_sizes; (void)n_in; (void)out_size;
    const int*   X    = (const int*)d_in[0];
    const float* C    = (const float*)d_in[1];
    const float* Ui1  = (const float*)d_in[2];
    const float* Vi1  = (const float*)d_in[3];
    const float* Ui2  = (const float*)d_in[4];
    const float* Vi2  = (const float*)d_in[5];
    const float* bi   = (const float*)d_in[6];
    const float* Uf1  = (const float*)d_in[7];
    const float* Vf1  = (const float*)d_in[8];
    const float* Uf2  = (const float*)d_in[9];
    const float* Vf2  = (const float*)d_in[10];
    const float* bf   = (const float*)d_in[11];
    const float* Uc1  = (const float*)d_in[12];
    const float* Vc1  = (const float*)d_in[13];
    const float* Uc2  = (const float*)d_in[14];
    const float* Vc2  = (const float*)d_in[15];
    const float* bc   = (const float*)d_in[16];
    const float* Uo1  = (const float*)d_in[17];
    const float* Vo1  = (const float*)d_in[18];
    const float* Uo2  = (const float*)d_in[19];
    const float* Vo2  = (const float*)d_in[20];
    const float* bo   = (const float*)d_in[21];
    const float* Wout = (const float*)d_in[22];
    const float* bout = (const float*)d_in[23];
    float* out = (float*)d_out;

    embed_kernel<<<2048, 256>>>(X, C);
    zero_states<<<512, 256>>>();

    dim3 sgrid(4, 64);  // n-tiles x m-tiles
    for (int t = 0; t < TT; ++t) {
        // layer 1: gates = x_t @ U*1 + h1 @ V*1 + b*1
        lstm_step<<<sgrid, 256>>>(0, t, Ui1, Uf1, Uc1, Uo1, Vi1, Vf1, Vc1, Vo1,
                                  bi, bf, bc, bo);
        // layer 2: gates = h1n @ U*2 + h2 @ V*2 + b*1  (layer-1 biases, per reference)
        lstm_step<<<sgrid, 256>>>(1, t, Ui2, Uf2, Uc2, Uo2, Vi2, Vf2, Vc2, Vo2,
                                  bi, bf, bc, bo);
    }

    out_gemm<<<dim3(NCLASS / 64, BB / 64), 256>>>(Wout, bout, out);
}

// round 2
// speedup vs baseline: 1.9569x; 1.9569x over previous
#include <cuda_runtime.h>
#include <math.h>
#include <stdint.h>

#define BB     2048
#define TT     256
#define EMB    128
#define NH     256
#define NCLASS 32000
#define KB     32

// -------- persistent scratch (static device globals; no allocation) --------
// xU[t][b][4n+g] precomputed input projection (+bias), split in two 1GB halves
__device__ float g_xU0[(size_t)128 * BB * 1024];
__device__ float g_xU1[(size_t)128 * BB * 1024];
__device__ float g_W1p[256 * 1024];   // packed V*1  [k][4n+g], tf32-rounded
__device__ float g_W2p[512 * 1024];   // packed [U*2 ; V*2]
__device__ float g_U1p[128 * 1024];   // packed U*1 for xU gemm
__device__ float g_bp[1024];          // packed biases (fp32)
__device__ float g_h1[2][BB * NH];
__device__ float g_h2[2][BB * NH];
__device__ float g_c1[BB * NH];
__device__ float g_c2[BB * NH];

// -------- helpers --------
__device__ __forceinline__ uint32_t f2tf(float x) {
    uint32_t r; asm("cvt.rna.tf32.f32 %0, %1;" : "=r"(r) : "f"(x)); return r;
}
__device__ __forceinline__ float sigf(float x) { return 1.f / (1.f + __expf(-x)); }
__device__ __forceinline__ float tanhfa(float x) { return 2.f / (1.f + __expf(-2.f * x)) - 1.f; }

__device__ __forceinline__ void mma_tf32(float c[4], const uint32_t a[4], const uint32_t b[2]) {
    asm volatile(
        "mma.sync.aligned.m16n8k8.row.col.f32.tf32.tf32.f32 "
        "{%0,%1,%2,%3}, {%4,%5,%6,%7}, {%8,%9}, {%0,%1,%2,%3};\n"
        : "+f"(c[0]), "+f"(c[1]), "+f"(c[2]), "+f"(c[3])
        : "r"(a[0]), "r"(a[1]), "r"(a[2]), "r"(a[3]), "r"(b[0]), "r"(b[1]));
}

// -------- weight packing: dst[k][4n+g] = tf32(src_g[k][n]) --------
__global__ void pack4(float* dst, const float* s0, const float* s1,
                      const float* s2, const float* s3, int K) {
    int i = blockIdx.x * blockDim.x + threadIdx.x;
    if (i < K * 256) {
        int base = (i >> 8) * 1024 + ((i & 255) << 2);
        dst[base + 0] = __uint_as_float(f2tf(s0[i]));
        dst[base + 1] = __uint_as_float(f2tf(s1[i]));
        dst[base + 2] = __uint_as_float(f2tf(s2[i]));
        dst[base + 3] = __uint_as_float(f2tf(s3[i]));
    }
}

__global__ void pack_b(const float* b0, const float* b1, const float* b2, const float* b3) {
    int n = threadIdx.x;
    g_bp[4 * n + 0] = b0[n];
    g_bp[4 * n + 1] = b1[n];
    g_bp[4 * n + 2] = b2[n];
    g_bp[4 * n + 3] = b3[n];
}

__global__ void zero_states() {
    const int n = BB * NH;
    for (int i = blockIdx.x * blockDim.x + threadIdx.x; i < n; i += gridDim.x * blockDim.x) {
        g_h1[0][i] = 0.f; g_h2[0][i] = 0.f; g_c1[i] = 0.f; g_c2[i] = 0.f;
    }
}

// ==========================================================================
// xU precompute: xU[t*2048+b][c] = sum_k tf32(C[X[b][t]][k]) * U1p[k][c] + bp[c]
// M = 524288, N = 1024, K = 128.  Tile 128x128, KB=32.
// ==========================================================================
__global__ __launch_bounds__(256) void xu_gemm(const int* __restrict__ X,
                                               const float* __restrict__ C) {
    __shared__ float sA[KB][136];
    __shared__ float sB[KB][136];
    const int tid = threadIdx.x;
    const int warp = tid >> 5, lane = tid & 31;
    const int gid = lane >> 2, tig = lane & 3;
    const int wR = warp >> 2, wC = warp & 3;
    const int mBase = blockIdx.y * 128;
    const int nBase = blockIdx.x * 128;

    // token for this thread's A rows (each thread stages half of one row: 4 f4)
    const int arow = tid >> 1;                     // 0..127
    const int r_glob = mBase + arow;
    const int t_idx = r_glob >> 11, b_idx = r_glob & 2047;
    const int tok = X[b_idx * TT + t_idx];
    const float* Arow = C + (size_t)tok * EMB;
    const int kq0 = (tid & 1) * 4;                 // float4 index base 0 or 4

    float acc[4][4][4];
#pragma unroll
    for (int mt = 0; mt < 4; ++mt)
#pragma unroll
        for (int nt = 0; nt < 4; ++nt)
#pragma unroll
            for (int q = 0; q < 4; ++q) acc[mt][nt][q] = 0.f;

    float4 pa[4], pb[4];
#pragma unroll
    for (int i = 0; i < 4; ++i)
        pa[i] = *(const float4*)&Arow[(kq0 + i) * 4];
#pragma unroll
    for (int i = 0; i < 4; ++i) {
        int id = tid * 4 + i; int k = id >> 5, n4 = (id & 31) * 4;
        pb[i] = *(const float4*)&g_U1p[(size_t)k * 1024 + nBase + n4];
    }

#pragma unroll 1
    for (int kb = 0; kb < EMB; kb += KB) {
#pragma unroll
        for (int i = 0; i < 4; ++i) {
            int k4 = kq0 * 4 + i * 4 - (kq0 ? 16 : 0); // = (kq0+i)*4 - kb? handled below
        }
        // store A (transposed, cvt) : thread covers k4 = (kq0+i)*4 within current stage
#pragma unroll
        for (int i = 0; i < 4; ++i) {
            int kk = (kq0 + i) * 4 - 0;  // local k of this float4 within stage (0..28)
            sA[kk + 0][arow] = __uint_as_float(f2tf(pa[i].x));
            sA[kk + 1][arow] = __uint_as_float(f2tf(pa[i].y));
            sA[kk + 2][arow] = __uint_as_float(f2tf(pa[i].z));
            sA[kk + 3][arow] = __uint_as_float(f2tf(pa[i].w));
        }
#pragma unroll
        for (int i = 0; i < 4; ++i) {
            int id = tid * 4 + i; int k = id >> 5, n4 = (id & 31) * 4;
            *(float4*)&sB[k][n4] = pb[i];
        }
        __syncthreads();
        if (kb + KB < EMB) {
#pragma unroll
            for (int i = 0; i < 4; ++i)
                pa[i] = *(const float4*)&Arow[kb + KB + (kq0 + i) * 4];
#pragma unroll
            for (int i = 0; i < 4; ++i) {
                int id = tid * 4 + i; int k = id >> 5, n4 = (id & 31) * 4;
                pb[i] = *(const float4*)&g_U1p[(size_t)(kb + KB + k) * 1024 + nBase + n4];
            }
        }
#pragma unroll
        for (int k8 = 0; k8 < KB; k8 += 8) {
            uint32_t af[4][4], bf_[4][2];
#pragma unroll
            for (int mt = 0; mt < 4; ++mt) {
                int r = wR * 64 + mt * 16 + gid;
                af[mt][0] = __float_as_uint(sA[k8 + tig][r]);
                af[mt][1] = __float_as_uint(sA[k8 + tig][r + 8]);
                af[mt][2] = __float_as_uint(sA[k8 + tig + 4][r]);
                af[mt][3] = __float_as_uint(sA[k8 + tig + 4][r + 8]);
            }
#pragma unroll
            for (int nt = 0; nt < 4; ++nt) {
                int c = wC * 32 + nt * 8 + gid;
                bf_[nt][0] = __float_as_uint(sB[k8 + tig][c]);
                bf_[nt][1] = __float_as_uint(sB[k8 + tig + 4][c]);
            }
#pragma unroll
            for (int mt = 0; mt < 4; ++mt)
#pragma unroll
                for (int nt = 0; nt < 4; ++nt)
                    mma_tf32(acc[mt][nt], af[mt], bf_[nt]);
        }
        __syncthreads();
    }

    // epilogue: add packed bias, write fp32
    const int t_tile = mBase >> 11;
    float* xu = (t_tile < 128) ? g_xU0 : g_xU1;
    const size_t rowoff = (size_t)(mBase & ((128 << 11) - 1));  // offset rows within half
#pragma unroll
    for (int nt = 0; nt < 4; ++nt) {
        int c0 = nBase + wC * 32 + nt * 8 + 2 * tig;
        float2 bb = *(const float2*)&g_bp[c0];
#pragma unroll
        for (int mt = 0; mt < 4; ++mt) {
            int r0 = wR * 64 + mt * 16 + gid;
            float2 v0 = make_float2(acc[mt][nt][0] + bb.x, acc[mt][nt][1] + bb.y);
            float2 v1 = make_float2(acc[mt][nt][2] + bb.x, acc[mt][nt][3] + bb.y);
            *(float2*)&xu[(rowoff + r0) * 1024 + c0] = v0;
            *(float2*)&xu[(rowoff + r0 + 8) * 1024 + c0] = v1;
        }
    }
}

// ==========================================================================
// LSTM step: gates = A @ Wp (+ xU or +bias), fused cell update.
// layer 0: A = h1_old (K=256), Wp = W1p, addend = xU[t]
// layer 1: A = [h1_new ; h2_old] (K=512), Wp = W2p, addend = packed bias
// Tile 128 x 128(packed = 32 n x 4 gates). Grid (8, 16).
// ==========================================================================
__global__ __launch_bounds__(256) void lstm_step_mma(int layer, int t) {
    __shared__ float sA[KB][136];
    __shared__ float sB[KB][136];
    const int tid = threadIdx.x;
    const int warp = tid >> 5, lane = tid & 31;
    const int gid = lane >> 2, tig = lane & 3;
    const int wR = warp >> 2, wC = warp & 3;
    const int mBase = blockIdx.y * 128;
    const int nBase = blockIdx.x * 128;

    const float* h1o = g_h1[t & 1];
    float* h1n = g_h1[(t + 1) & 1];
    const float* h2o = g_h2[t & 1];
    float* h2n = g_h2[(t + 1) & 1];

    const float* A0; const float* A1; const float* Wp; int K;
    float* cst; float* hout;
    if (layer == 0) { A0 = h1o; A1 = h1o; Wp = g_W1p; K = 256; cst = g_c1; hout = h1n; }
    else            { A0 = h1n; A1 = h2o; Wp = g_W2p; K = 512; cst = g_c2; hout = h2n; }

    float acc[4][4][4];
#pragma unroll
    for (int mt = 0; mt < 4; ++mt)
#pragma unroll
        for (int nt = 0; nt < 4; ++nt)
#pragma unroll
            for (int q = 0; q < 4; ++q) acc[mt][nt][q] = 0.f;

    const int arow = tid >> 1;
    const int kq0 = (tid & 1) * 4;

    float4 pa[4], pb[4];
    {
        const float* Asrc = A0;
#pragma unroll
        for (int i = 0; i < 4; ++i)
            pa[i] = *(const float4*)&Asrc[(size_t)(mBase + arow) * NH + (kq0 + i) * 4];
#pragma unroll
        for (int i = 0; i < 4; ++i) {
            int id = tid * 4 + i; int k = id >> 5, n4 = (id & 31) * 4;
            pb[i] = *(const float4*)&Wp[(size_t)k * 1024 + nBase + n4];
        }
    }

#pragma unroll 1
    for (int kb = 0; kb < K; kb += KB) {
#pragma unroll
        for (int i = 0; i < 4; ++i) {
            int kk = (kq0 + i) * 4;
            sA[kk + 0][arow] = __uint_as_float(f2tf(pa[i].x));
            sA[kk + 1][arow] = __uint_as_float(f2tf(pa[i].y));
            sA[kk + 2][arow] = __uint_as_float(f2tf(pa[i].z));
            sA[kk + 3][arow] = __uint_as_float(f2tf(pa[i].w));
        }
#pragma unroll
        for (int i = 0; i < 4; ++i) {
            int id = tid * 4 + i; int k = id >> 5, n4 = (id & 31) * 4;
            *(float4*)&sB[k][n4] = pb[i];
        }
        __syncthreads();
        if (kb + KB < K) {
            int kn = kb + KB;
            const float* Asrc = (kn < 256) ? A0 : A1;
            int kk = kn & 255;
#pragma unroll
            for (int i = 0; i < 4; ++i)
                pa[i] = *(const float4*)&Asrc[(size_t)(mBase + arow) * NH + kk + (kq0 + i) * 4];
#pragma unroll
            for (int i = 0; i < 4; ++i) {
                int id = tid * 4 + i; int k = id >> 5, n4 = (id & 31) * 4;
                pb[i] = *(const float4*)&Wp[(size_t)(kn + k) * 1024 + nBase + n4];
            }
        }
#pragma unroll
        for (int k8 = 0; k8 < KB; k8 += 8) {
            uint32_t af[4][4], bf_[4][2];
#pragma unroll
            for (int mt = 0; mt < 4; ++mt) {
                int r = wR * 64 + mt * 16 + gid;
                af[mt][0] = __float_as_uint(sA[k8 + tig][r]);
                af[mt][1] = __float_as_uint(sA[k8 + tig][r + 8]);
                af[mt][2] = __float_as_uint(sA[k8 + tig + 4][r]);
                af[mt][3] = __float_as_uint(sA[k8 + tig + 4][r + 8]);
            }
#pragma unroll
            for (int nt = 0; nt < 4; ++nt) {
                int c = wC * 32 + nt * 8 + gid;
                bf_[nt][0] = __float_as_uint(sB[k8 + tig][c]);
                bf_[nt][1] = __float_as_uint(sB[k8 + tig + 4][c]);
            }
#pragma unroll
            for (int mt = 0; mt < 4; ++mt)
#pragma unroll
                for (int nt = 0; nt < 4; ++nt)
                    mma_tf32(acc[mt][nt], af[mt], bf_[nt]);
        }
        __syncthreads();
    }

    // ---- fused LSTM cell epilogue ----
    // thread (tig even) -> row gid has gates g0,g1 in regs; partner (tig^1) has g2,g3.
    const float* xu = (t < 128) ? g_xU0 : g_xU1;
    const size_t xu_t = (size_t)(t & 127) * BB * 1024;
    const bool tlow = ((tig & 1) == 0);
#pragma unroll
    for (int nt = 0; nt < 4; ++nt) {
        int c0 = nBase + wC * 32 + nt * 8 + 2 * tig;   // packed col of q0
        int n = c0 >> 2;
#pragma unroll
        for (int mt = 0; mt < 4; ++mt) {
            float q0 = acc[mt][nt][0], q1 = acc[mt][nt][1];
            float q2 = acc[mt][nt][2], q3 = acc[mt][nt][3];
            float x0 = tlow ? q2 : q0;
            float x1 = tlow ? q3 : q1;
            float y0 = __shfl_xor_sync(0xffffffffu, x0, 1);
            float y1 = __shfl_xor_sync(0xffffffffu, x1, 1);
            float gI, gF, gG, gO;
            int row;
            if (tlow) { gI = q0; gF = q1; gG = y0; gO = y1; row = mBase + wR * 64 + mt * 16 + gid; }
            else      { gI = y0; gF = y1; gG = q2; gO = q3; row = mBase + wR * 64 + mt * 16 + gid + 8; }
            float a0, a1, a2, a3;
            if (layer == 0) {
                float4 x4 = *(const float4*)&xu[xu_t + (size_t)row * 1024 + (n << 2)];
                a0 = x4.x; a1 = x4.y; a2 = x4.z; a3 = x4.w;
            } else {
                float4 b4 = *(const float4*)&g_bp[n << 2];
                a0 = b4.x; a1 = b4.y; a2 = b4.z; a3 = b4.w;
            }
            float si = sigf(gI + a0);
            float sf = sigf(gF + a1);
            float sg = tanhfa(gG + a2);
            float so = sigf(gO + a3);
            size_t off = (size_t)row * NH + n;
            float cn = cst[off] * sf + si * sg;
            cst[off] = cn;
            hout[off] = so * tanhfa(cn);
        }
    }
}

// ==========================================================================
// Output GEMM: out = h2 @ W_out + b_out.  M=2048, N=32000, K=256.
// ==========================================================================
__global__ __launch_bounds__(256) void out_gemm_mma(const float* __restrict__ Wout,
                                                    const float* __restrict__ bout,
                                                    float* __restrict__ out) {
    __shared__ float sA[KB][136];
    __shared__ float sB[KB][136];
    const int tid = threadIdx.x;
    const int warp = tid >> 5, lane = tid & 31;
    const int gid = lane >> 2, tig = lane & 3;
    const int wR = warp >> 2, wC = warp & 3;
    const int mBase = blockIdx.y * 128;
    const int nBase = blockIdx.x * 128;
    const float* h2 = g_h2[0];

    float acc[4][4][4];
#pragma unroll
    for (int mt = 0; mt < 4; ++mt)
#pragma unroll
        for (int nt = 0; nt < 4; ++nt)
#pragma unroll
            for (int q = 0; q < 4; ++q) acc[mt][nt][q] = 0.f;

    const int arow = tid >> 1;
    const int kq0 = (tid & 1) * 4;

    float4 pa[4], pb[4];
#pragma unroll
    for (int i = 0; i < 4; ++i)
        pa[i] = *(const float4*)&h2[(size_t)(mBase + arow) * NH + (kq0 + i) * 4];
#pragma unroll
    for (int i = 0; i < 4; ++i) {
        int id = tid * 4 + i; int k = id >> 5, n4 = (id & 31) * 4;
        pb[i] = *(const float4*)&Wout[(size_t)k * NCLASS + nBase + n4];
    }

#pragma unroll 1
    for (int kb = 0; kb < NH; kb += KB) {
#pragma unroll
        for (int i = 0; i < 4; ++i) {
            int kk = (kq0 + i) * 4;
            sA[kk + 0][arow] = __uint_as_float(f2tf(pa[i].x));
            sA[kk + 1][arow] = __uint_as_float(f2tf(pa[i].y));
            sA[kk + 2][arow] = __uint_as_float(f2tf(pa[i].z));
            sA[kk + 3][arow] = __uint_as_float(f2tf(pa[i].w));
        }
#pragma unroll
        for (int i = 0; i < 4; ++i) {
            int id = tid * 4 + i; int k = id >> 5, n4 = (id & 31) * 4;
            float4 v = pb[i];
            v.x = __uint_as_float(f2tf(v.x)); v.y = __uint_as_float(f2tf(v.y));
            v.z = __uint_as_float(f2tf(v.z)); v.w = __uint_as_float(f2tf(v.w));
            *(float4*)&sB[k][n4] = v;
        }
        __syncthreads();
        if (kb + KB < NH) {
#pragma unroll
            for (int i = 0; i < 4; ++i)
                pa[i] = *(const float4*)&h2[(size_t)(mBase + arow) * NH + kb + KB + (kq0 + i) * 4];
#pragma unroll
            for (int i = 0; i < 4; ++i) {
                int id = tid * 4 + i; int k = id >> 5, n4 = (id & 31) * 4;
                pb[i] = *(const float4*)&Wout[(size_t)(kb + KB + k) * NCLASS + nBase + n4];
            }
        }
#pragma unroll
        for (int k8 = 0; k8 < KB; k8 += 8) {
            uint32_t af[4][4], bf_[4][2];
#pragma unroll
            for (int mt = 0; mt < 4; ++mt) {
                int r = wR * 64 + mt * 16 + gid;
                af[mt][0] = __float_as_uint(sA[k8 + tig][r]);
                af[mt][1] = __float_as_uint(sA[k8 + tig][r + 8]);
                af[mt][2] = __float_as_uint(sA[k8 + tig + 4][r]);
                af[mt][3] = __float_as_uint(sA[k8 + tig + 4][r + 8]);
            }
#pragma unroll
            for (int nt = 0; nt < 4; ++nt) {
                int c = wC * 32 + nt * 8 + gid;
                bf_[nt][0] = __float_as_uint(sB[k8 + tig][c]);
                bf_[nt][1] = __float_as_uint(sB[k8 + tig + 4][c]);
            }
#pragma unroll
            for (int mt = 0; mt < 4; ++mt)
#pragma unroll
                for (int nt = 0; nt < 4; ++nt)
                    mma_tf32(acc[mt][nt], af[mt], bf_[nt]);
        }
        __syncthreads();
    }

#pragma unroll
    for (int nt = 0; nt < 4; ++nt) {
        int c0 = nBase + wC * 32 + nt * 8 + 2 * tig;
        float2 bb = *(const float2*)&bout[c0];
#pragma unroll
        for (int mt = 0; mt < 4; ++mt) {
            int r0 = mBase + wR * 64 + mt * 16 + gid;
            float2 v0 = make_float2(acc[mt][nt][0] + bb.x, acc[mt][nt][1] + bb.y);
            float2 v1 = make_float2(acc[mt][nt][2] + bb.x, acc[mt][nt][3] + bb.y);
            *(float2*)&out[(size_t)r0 * NCLASS + c0] = v0;
            *(float2*)&out[(size_t)(r0 + 8) * NCLASS + c0] = v1;
        }
    }
}

// -------- launch --------
extern "C" void kernel_launch(void* const* d_in, const int* in_sizes, int n_in,
                              void* d_out, int out_size) {
    (void)in_sizes; (void)n_in; (void)out_size;
    const int*   X    = (const int*)d_in[0];
    const float* C    = (const float*)d_in[1];
    const float* Ui1  = (const float*)d_in[2];
    const float* Vi1  = (const float*)d_in[3];
    const float* Ui2  = (const float*)d_in[4];
    const float* Vi2  = (const float*)d_in[5];
    const float* bi   = (const float*)d_in[6];
    const float* Uf1  = (const float*)d_in[7];
    const float* Vf1  = (const float*)d_in[8];
    const float* Uf2  = (const float*)d_in[9];
    const float* Vf2  = (const float*)d_in[10];
    const float* bf   = (const float*)d_in[11];
    const float* Uc1  = (const float*)d_in[12];
    const float* Vc1  = (const float*)d_in[13];
    const float* Uc2  = (const float*)d_in[14];
    const float* Vc2  = (const float*)d_in[15];
    const float* bc   = (const float*)d_in[16];
    const float* Uo1  = (const float*)d_in[17];
    const float* Vo1  = (const float*)d_in[18];
    const float* Uo2  = (const float*)d_in[19];
    const float* Vo2  = (const float*)d_in[20];
    const float* bo   = (const float*)d_in[21];
    const float* Wout = (const float*)d_in[22];
    const float* bout = (const float*)d_in[23];
    float* out = (float*)d_out;

    float* W1p; cudaGetSymbolAddress((void**)&W1p, g_W1p);
    float* W2p; cudaGetSymbolAddress((void**)&W2p, g_W2p);
    float* U1p; cudaGetSymbolAddress((void**)&U1p, g_U1p);

    pack4<<<(256 * 256) / 256, 256>>>(W1p, Vi1, Vf1, Vc1, Vo1, 256);
    pack4<<<(256 * 256) / 256, 256>>>(W2p, Ui2, Uf2, Uc2, Uo2, 256);
    pack4<<<(256 * 256) / 256, 256>>>(W2p + 256 * 1024, Vi2, Vf2, Vc2, Vo2, 256);
    pack4<<<(128 * 256) / 256, 256>>>(U1p, Ui1, Uf1, Uc1, Uo1, 128);
    pack_b<<<1, 256>>>(bi, bf, bc, bo);
    zero_states<<<512, 256>>>();

    // xU = embed @ U1 + b   (M = T*B = 524288)
    xu_gemm<<<dim3(8, 4096), 256>>>(X, C);

    dim3 sgrid(8, 16);
    for (int t = 0; t < TT; ++t) {
        lstm_step_mma<<<sgrid, 256>>>(0, t);
        lstm_step_mma<<<sgrid, 256>>>(1, t);
    }

    out_gemm_mma<<<dim3(NCLASS / 128, BB / 128), 256>>>(Wout, bout, out);
}